// round 1
// baseline (speedup 1.0000x reference)
#include <cuda_runtime.h>
#include <cstdint>

// Problem constants (fixed by the reference setup).
#define BATCH 16
#define SEQ   4096
#define DIM   256          // floats per frame
#define QUADS (DIM / 4)    // 64 float4 per frame
#define MAXT  (SEQ * 7)    // durations are in [0,8) -> total <= 7*4096 = 28672

// Scratch: inverse map from output frame -> source sequence index (-1 = padding).
__device__ int g_idx[BATCH * MAXT];

// ---------------------------------------------------------------------------
// Kernel 1: per-batch block scan of durations + scatter of the inverse map.
// One block (1024 threads) per batch. Each thread owns 4 consecutive s values.
// ---------------------------------------------------------------------------
__global__ __launch_bounds__(1024) void scan_scatter_kernel(
    const int* __restrict__ dims,  // [B, S] (trailing dim of 1 squeezed)
    int T)
{
    const int b   = blockIdx.x;
    const int tid = threadIdx.x;           // 0..1023
    const int lane = tid & 31;
    const int warp = tid >> 5;

    // Vectorized load of this thread's 4 durations.
    const int4 dv = reinterpret_cast<const int4*>(dims + (size_t)b * SEQ)[tid];
    int d0[4] = {dv.x, dv.y, dv.z, dv.w};
    int sum = d0[0] + d0[1] + d0[2] + d0[3];

    // Inclusive warp scan of per-thread sums.
    int v = sum;
    #pragma unroll
    for (int off = 1; off < 32; off <<= 1) {
        int n = __shfl_up_sync(0xFFFFFFFFu, v, off);
        if (lane >= off) v += n;
    }

    __shared__ int warp_sums[32];
    if (lane == 31) warp_sums[warp] = v;
    __syncthreads();

    if (warp == 0) {
        int w = warp_sums[lane];
        #pragma unroll
        for (int off = 1; off < 32; off <<= 1) {
            int n = __shfl_up_sync(0xFFFFFFFFu, w, off);
            if (lane >= off) w += n;
        }
        warp_sums[lane] = w;   // inclusive scan of warp totals
    }
    __syncthreads();

    const int warp_excl = (warp > 0) ? warp_sums[warp - 1] : 0;
    int start = warp_excl + (v - sum);         // exclusive prefix before s = tid*4
    const int total = warp_sums[31];           // this batch's expanded length

    int* __restrict__ ib = g_idx + (size_t)b * T;
    const int base_s = tid * 4;

    // Scatter: output frames [start, start+d) map to source row s.
    #pragma unroll
    for (int j = 0; j < 4; j++) {
        const int dj = d0[j];
        for (int k = 0; k < dj; k++) ib[start + k] = base_s + j;
        start += dj;
    }

    // Padding tail -> -1 (gather writes zeros there).
    for (int t = total + tid; t < T; t += 1024) ib[t] = -1;
}

// ---------------------------------------------------------------------------
// Kernel 2: gather. 64 threads per output frame, one float4 each.
// Block = 256 threads = 4 frames.
// ---------------------------------------------------------------------------
__global__ __launch_bounds__(256) void gather_kernel(
    const float* __restrict__ x,   // [B, S, D]
    float* __restrict__ out,       // [B, T, D]
    int T)
{
    const long frame = (long)blockIdx.x * 4 + (threadIdx.x >> 6);
    const int  q     = threadIdx.x & 63;                 // float4 index within frame
    const long total_frames = (long)BATCH * T;
    if (frame >= total_frames) return;

    const int b = (int)(frame / T);
    const int idx = g_idx[frame];                        // broadcast across 64 threads

    float4* __restrict__ o = reinterpret_cast<float4*>(out) + frame * QUADS + q;
    if (idx < 0) {
        *o = make_float4(0.f, 0.f, 0.f, 0.f);
    } else {
        const float4* __restrict__ src =
            reinterpret_cast<const float4*>(x + ((size_t)b * SEQ + idx) * DIM) + q;
        *o = *src;
    }
}

extern "C" void kernel_launch(void* const* d_in, const int* in_sizes, int n_in,
                              void* d_out, int out_size)
{
    const float* x    = (const float*)d_in[0];   // [B, S, D] float32
    const int*   dims = (const int*)d_in[1];     // [B, S, 1] int32
    float*       out  = (float*)d_out;           // [B, T, D] float32

    const int T = out_size / (BATCH * DIM);

    scan_scatter_kernel<<<BATCH, 1024>>>(dims, T);

    const long total_frames = (long)BATCH * T;
    const int  grid = (int)((total_frames + 3) / 4);
    gather_kernel<<<grid, 256>>>(x, out, T);
}

// round 2
// speedup vs baseline: 1.4517x; 1.4517x over previous
#include <cuda_runtime.h>
#include <cstdint>

// Problem constants (fixed by the reference setup).
#define BATCH 16
#define SEQ   4096
#define DIM   256          // floats per frame
#define QUADS (DIM / 4)    // 64 float4 per frame
#define MAXT  (SEQ * 7)    // durations in [0,8) -> total <= 7*4096 = 28672

// Scratch: inverse map from output frame -> source sequence index (-1 = padding).
__device__ int g_idx[BATCH * MAXT];

// ---------------------------------------------------------------------------
// Kernel 1: per-batch block scan of durations + scatter of the inverse map.
// One block (1024 threads) per batch. Each thread owns 4 consecutive s values.
// ---------------------------------------------------------------------------
__global__ __launch_bounds__(1024) void scan_scatter_kernel(
    const int* __restrict__ dims,  // [B, S] (trailing dim of 1 squeezed)
    int T)
{
    const int b    = blockIdx.x;
    const int tid  = threadIdx.x;          // 0..1023
    const int lane = tid & 31;
    const int warp = tid >> 5;

    // Vectorized load of this thread's 4 durations.
    const int4 dv = reinterpret_cast<const int4*>(dims + (size_t)b * SEQ)[tid];
    int d0[4] = {dv.x, dv.y, dv.z, dv.w};
    int sum = d0[0] + d0[1] + d0[2] + d0[3];

    // Inclusive warp scan of per-thread sums.
    int v = sum;
    #pragma unroll
    for (int off = 1; off < 32; off <<= 1) {
        int n = __shfl_up_sync(0xFFFFFFFFu, v, off);
        if (lane >= off) v += n;
    }

    __shared__ int warp_sums[32];
    if (lane == 31) warp_sums[warp] = v;
    __syncthreads();

    if (warp == 0) {
        int w = warp_sums[lane];
        #pragma unroll
        for (int off = 1; off < 32; off <<= 1) {
            int n = __shfl_up_sync(0xFFFFFFFFu, w, off);
            if (lane >= off) w += n;
        }
        warp_sums[lane] = w;   // inclusive scan of warp totals
    }
    __syncthreads();

    const int warp_excl = (warp > 0) ? warp_sums[warp - 1] : 0;
    int start = warp_excl + (v - sum);       // exclusive prefix before s = tid*4
    const int total = warp_sums[31];         // this batch's expanded length

    int* __restrict__ ib = g_idx + (size_t)b * T;
    const int base_s = tid * 4;

    // Scatter: output frames [start, start+d) map to source row s.
    #pragma unroll
    for (int j = 0; j < 4; j++) {
        const int dj = d0[j];
        for (int k = 0; k < dj; k++) ib[start + k] = base_s + j;
        start += dj;
    }

    // Padding tail -> -1 (gather writes zeros there).
    for (int t = total + tid; t < T; t += 1024) ib[t] = -1;
}

// ---------------------------------------------------------------------------
// Kernel 2: gather. 16 threads per frame, 4 float4 each (stride-16 interleave
// => every LDG.128/STG.128 is fully coalesced). Block = 256 threads = 16 frames.
// 4 independent loads in flight per thread (MLP=4), streaming stores (__stcs)
// keep the write stream from evicting the x working set out of L2.
// ---------------------------------------------------------------------------
__global__ __launch_bounds__(256) void gather_kernel(
    const float* __restrict__ x,   // [B, S, D]
    float* __restrict__ out,       // [B, T, D]
    int T)
{
    const int b          = blockIdx.y;
    const int frame_in_b = blockIdx.x * 16 + (threadIdx.x >> 4);
    if (frame_in_b >= T) return;

    const int  q     = threadIdx.x & 15;             // float4 lane within frame
    const long frame = (long)b * T + frame_in_b;
    const int  idx   = g_idx[frame];                 // broadcast across 16 threads

    float4* __restrict__ o = reinterpret_cast<float4*>(out) + frame * QUADS + q;

    if (idx < 0) {
        const float4 z = make_float4(0.f, 0.f, 0.f, 0.f);
        __stcs(o +  0, z);
        __stcs(o + 16, z);
        __stcs(o + 32, z);
        __stcs(o + 48, z);
    } else {
        const float4* __restrict__ s =
            reinterpret_cast<const float4*>(x + ((size_t)b * SEQ + idx) * DIM) + q;
        const float4 v0 = __ldg(s +  0);
        const float4 v1 = __ldg(s + 16);
        const float4 v2 = __ldg(s + 32);
        const float4 v3 = __ldg(s + 48);
        __stcs(o +  0, v0);
        __stcs(o + 16, v1);
        __stcs(o + 32, v2);
        __stcs(o + 48, v3);
    }
}

extern "C" void kernel_launch(void* const* d_in, const int* in_sizes, int n_in,
                              void* d_out, int out_size)
{
    const float* x    = (const float*)d_in[0];   // [B, S, D] float32
    const int*   dims = (const int*)d_in[1];     // [B, S, 1] int32
    float*       out  = (float*)d_out;           // [B, T, D] float32

    const int T = out_size / (BATCH * DIM);

    scan_scatter_kernel<<<BATCH, 1024>>>(dims, T);

    dim3 grid((T + 15) / 16, BATCH);
    gather_kernel<<<grid, 256>>>(x, out, T);
}

// round 3
// speedup vs baseline: 1.5437x; 1.0634x over previous
#include <cuda_runtime.h>
#include <cstdint>

// Problem constants (fixed by the reference setup).
#define BATCH 16
#define SEQ   4096
#define DIM   256          // floats per frame
#define QUADS (DIM / 4)    // 64 float4 per frame
#define MAXT  (SEQ * 7)    // durations in [0,8) -> total <= 7*4096 = 28672

// Scratch (static __device__ arrays; no allocation allowed).
__device__ int g_idx [BATCH * MAXT];   // output frame -> source s (-1 = padding)
__device__ int g_pref[BATCH * SEQ];    // exclusive prefix of durations per (b,s)

// ---------------------------------------------------------------------------
// Kernel A: per-batch block scan of durations -> exclusive prefixes + tail fill.
// One block (1024 threads) per batch; each thread owns 4 consecutive s values.
// ---------------------------------------------------------------------------
__global__ __launch_bounds__(1024) void scan_kernel(
    const int* __restrict__ dims,  // [B, S]
    int T)
{
    const int b    = blockIdx.x;
    const int tid  = threadIdx.x;          // 0..1023
    const int lane = tid & 31;
    const int warp = tid >> 5;

    const int4 dv = reinterpret_cast<const int4*>(dims + (size_t)b * SEQ)[tid];
    const int sum = dv.x + dv.y + dv.z + dv.w;

    // Inclusive warp scan of per-thread sums.
    int v = sum;
    #pragma unroll
    for (int off = 1; off < 32; off <<= 1) {
        int n = __shfl_up_sync(0xFFFFFFFFu, v, off);
        if (lane >= off) v += n;
    }

    __shared__ int warp_sums[32];
    if (lane == 31) warp_sums[warp] = v;
    __syncthreads();

    if (warp == 0) {
        int w = warp_sums[lane];
        #pragma unroll
        for (int off = 1; off < 32; off <<= 1) {
            int n = __shfl_up_sync(0xFFFFFFFFu, w, off);
            if (lane >= off) w += n;
        }
        warp_sums[lane] = w;   // inclusive scan of warp totals
    }
    __syncthreads();

    const int warp_excl = (warp > 0) ? warp_sums[warp - 1] : 0;
    const int start = warp_excl + (v - sum);   // exclusive prefix before s = tid*4
    const int total = warp_sums[31];           // this batch's expanded length

    // Exclusive prefixes for this thread's 4 s values (coalesced int4 store).
    int4 p;
    p.x = start;
    p.y = p.x + dv.x;
    p.z = p.y + dv.y;
    p.w = p.z + dv.z;
    reinterpret_cast<int4*>(g_pref + (size_t)b * SEQ)[tid] = p;

    // Padding tail -> -1.
    int* __restrict__ ib = g_idx + (size_t)b * T;
    for (int t = total + tid; t < T; t += 1024) ib[t] = -1;
}

// ---------------------------------------------------------------------------
// Kernel B: parallel scatter of the inverse map. One thread per (b, s);
// each thread writes d[s] (<= 7) consecutive ints. 256 blocks of 256.
// ---------------------------------------------------------------------------
__global__ __launch_bounds__(256) void scatter_kernel(
    const int* __restrict__ dims,  // [B, S]
    int T)
{
    const int g = blockIdx.x * 256 + threadIdx.x;   // 0 .. B*SEQ-1
    const int b = g >> 12;                          // SEQ = 4096
    const int s = g & (SEQ - 1);

    const int d     = dims[g];
    const int start = g_pref[g];

    int* __restrict__ ib = g_idx + (size_t)b * T + start;
    for (int k = 0; k < d; k++) ib[k] = s;
}

// ---------------------------------------------------------------------------
// Kernel C: gather. 8 threads per frame, 8 float4 each (stride-8 interleave
// => every LDG.128/STG.128 is fully coalesced; 4 frames per warp). MLP=8.
// Streaming stores keep the write stream from evicting x out of L2.
// ---------------------------------------------------------------------------
__global__ __launch_bounds__(256) void gather_kernel(
    const float* __restrict__ x,   // [B, S, D]
    float* __restrict__ out,       // [B, T, D]
    int T)
{
    const int b          = blockIdx.y;
    const int frame_in_b = blockIdx.x * 32 + (threadIdx.x >> 3);
    if (frame_in_b >= T) return;

    const int  q     = threadIdx.x & 7;              // float4 lane within frame
    const long frame = (long)b * T + frame_in_b;
    const int  idx   = g_idx[frame];                 // broadcast across 8 threads

    float4* __restrict__ o = reinterpret_cast<float4*>(out) + frame * QUADS + q;

    if (idx < 0) {
        const float4 z = make_float4(0.f, 0.f, 0.f, 0.f);
        #pragma unroll
        for (int k = 0; k < 8; k++) __stcs(o + 8 * k, z);
    } else {
        const float4* __restrict__ s =
            reinterpret_cast<const float4*>(x + ((size_t)b * SEQ + idx) * DIM) + q;
        float4 v[8];
        #pragma unroll
        for (int k = 0; k < 8; k++) v[k] = __ldg(s + 8 * k);
        #pragma unroll
        for (int k = 0; k < 8; k++) __stcs(o + 8 * k, v[k]);
    }
}

extern "C" void kernel_launch(void* const* d_in, const int* in_sizes, int n_in,
                              void* d_out, int out_size)
{
    const float* x    = (const float*)d_in[0];   // [B, S, D] float32
    const int*   dims = (const int*)d_in[1];     // [B, S, 1] int32
    float*       out  = (float*)d_out;           // [B, T, D] float32

    const int T = out_size / (BATCH * DIM);

    scan_kernel<<<BATCH, 1024>>>(dims, T);
    scatter_kernel<<<(BATCH * SEQ) / 256, 256>>>(dims, T);

    dim3 grid((T + 31) / 32, BATCH);
    gather_kernel<<<grid, 256>>>(x, out, T);
}

// round 4
// speedup vs baseline: 1.6166x; 1.0472x over previous
#include <cuda_runtime.h>
#include <cstdint>

// Problem constants (fixed by the reference setup).
#define BATCH 16
#define SEQ   4096
#define DIM   256          // floats per frame
#define QUADS (DIM / 4)    // 64 float4 per frame

// Scratch (static __device__ arrays; no allocation allowed).
__device__ int2 g_meta [BATCH * SEQ];   // per (b,s): {exclusive start, duration}
__device__ int  g_total[BATCH];         // expanded length per batch

// ---------------------------------------------------------------------------
// Kernel 1: per-batch block scan of durations -> (start, d) meta + totals.
// One block (1024 threads) per batch; each thread owns 4 consecutive s values.
// ---------------------------------------------------------------------------
__global__ __launch_bounds__(1024) void scan_kernel(
    const int* __restrict__ dims)  // [B, S]
{
    const int b    = blockIdx.x;
    const int tid  = threadIdx.x;          // 0..1023
    const int lane = tid & 31;
    const int warp = tid >> 5;

    const int4 dv = reinterpret_cast<const int4*>(dims + (size_t)b * SEQ)[tid];
    const int sum = dv.x + dv.y + dv.z + dv.w;

    // Inclusive warp scan of per-thread sums.
    int v = sum;
    #pragma unroll
    for (int off = 1; off < 32; off <<= 1) {
        int n = __shfl_up_sync(0xFFFFFFFFu, v, off);
        if (lane >= off) v += n;
    }

    __shared__ int warp_sums[32];
    if (lane == 31) warp_sums[warp] = v;
    __syncthreads();

    if (warp == 0) {
        int w = warp_sums[lane];
        #pragma unroll
        for (int off = 1; off < 32; off <<= 1) {
            int n = __shfl_up_sync(0xFFFFFFFFu, w, off);
            if (lane >= off) w += n;
        }
        warp_sums[lane] = w;   // inclusive scan of warp totals
    }
    __syncthreads();

    const int warp_excl = (warp > 0) ? warp_sums[warp - 1] : 0;
    const int start = warp_excl + (v - sum);   // exclusive prefix before s = tid*4

    // Per-s meta: {start, d} packed as int2; 4 per thread -> two int4 stores.
    int2 m0, m1, m2, m3;
    m0.x = start;             m0.y = dv.x;
    m1.x = m0.x + dv.x;       m1.y = dv.y;
    m2.x = m1.x + dv.y;       m2.y = dv.z;
    m3.x = m2.x + dv.z;       m3.y = dv.w;
    int4* mp = reinterpret_cast<int4*>(g_meta + (size_t)b * SEQ) + tid * 2;
    mp[0] = make_int4(m0.x, m0.y, m1.x, m1.y);
    mp[1] = make_int4(m2.x, m2.y, m3.x, m3.y);

    if (tid == 0) g_total[b] = warp_sums[31];
}

// ---------------------------------------------------------------------------
// Kernel 2: expand. Two block roles:
//  - copy blocks: 8 warps/block, one warp per (b,s). Warp reads the 1KB source
//    row ONCE (2 LDG.128/lane), then streams it out d times to contiguous
//    destination frames (2x 512B-contiguous STG.128 per copy). Read traffic
//    through L2 drops to 64MB total (x read exactly once).
//  - zero-fill blocks: cover 64-frame stripes of [0,T) per batch; write zeros
//    only for frames >= total_b; stripes fully inside [0,total_b) exit fast.
// ---------------------------------------------------------------------------
#define NCOPY_BLOCKS ((BATCH * SEQ) / 8)     // 8192
#define ZF_FRAMES    64                       // frames per zero-fill block

__global__ __launch_bounds__(256) void expand_kernel(
    const float* __restrict__ x,   // [B, S, D]
    float* __restrict__ out,       // [B, T, D]
    int T, int zb_per_batch)
{
    const int tid = threadIdx.x;

    if (blockIdx.x < NCOPY_BLOCKS) {
        // ---- copy role ----
        const int warp = tid >> 5;
        const int lane = tid & 31;
        const int g    = blockIdx.x * 8 + warp;      // 0 .. B*SEQ-1
        const int b    = g >> 12;                    // SEQ = 4096

        const int2 meta = __ldg(&g_meta[g]);         // {start, d} broadcast
        const int  d    = meta.y;
        if (d == 0) return;

        const float4* __restrict__ src =
            reinterpret_cast<const float4*>(x) + (size_t)g * QUADS;
        const float4 v0 = __ldg(src + lane);
        const float4 v1 = __ldg(src + lane + 32);

        float4* __restrict__ o = reinterpret_cast<float4*>(out)
                               + ((size_t)b * T + meta.x) * QUADS;
        for (int c = 0; c < d; c++) {
            __stcs(o + lane,      v0);
            __stcs(o + lane + 32, v1);
            o += QUADS;
        }
    } else {
        // ---- zero-fill role ----
        const int zb = blockIdx.x - NCOPY_BLOCKS;
        const int b  = zb / zb_per_batch;
        const int j  = zb - b * zb_per_batch;

        const int total = g_total[b];
        const int base_frame = j * ZF_FRAMES;
        if (base_frame + ZF_FRAMES <= total) return;   // stripe fully covered by copies

        const int base = base_frame * QUADS;           // float4 index within batch
        int end = (base_frame + ZF_FRAMES) * QUADS;
        const int tq = T * QUADS;
        if (end > tq) end = tq;
        const int lo = total * QUADS;                  // first padding float4

        float4* __restrict__ ob = reinterpret_cast<float4*>(out) + (size_t)b * tq;
        const float4 z = make_float4(0.f, 0.f, 0.f, 0.f);
        for (int e = base + tid; e < end; e += 256)
            if (e >= lo) __stcs(ob + e, z);
    }
}

extern "C" void kernel_launch(void* const* d_in, const int* in_sizes, int n_in,
                              void* d_out, int out_size)
{
    const float* x    = (const float*)d_in[0];   // [B, S, D] float32
    const int*   dims = (const int*)d_in[1];     // [B, S, 1] int32
    float*       out  = (float*)d_out;           // [B, T, D] float32

    const int T = out_size / (BATCH * DIM);
    const int zb_per_batch = (T + ZF_FRAMES - 1) / ZF_FRAMES;

    scan_kernel<<<BATCH, 1024>>>(dims);

    const int grid = NCOPY_BLOCKS + BATCH * zb_per_batch;
    expand_kernel<<<grid, 256>>>(x, out, T, zb_per_batch);
}